// round 2
// baseline (speedup 1.0000x reference)
#include <cuda_runtime.h>

// ValueLayerSlow: Pauli expectation values <psi|O|psi> for 16 Pauli strings on
// 10 qubits (dim=1024), states are REAL vectors (8*512 = 4096 states).
//
// Algebraic reduction (states real):
//   Z on bit b (ops 0..9, op o -> bit 9-o):  sum_d (-1)^{bit_b(d)} x_d^2
//   X on bit b (ops 10,11,12 -> bits 9,8,7): sum_d x_d * x_{d^mask}
//   Y ops (13,14,15): exactly 0 (real part of purely-imaginary form).
//
// One warp per state. Lane t holds elements d = i*128 + t*4 + j (8 x float4).
//   - X partners flip bits of i -> register-resident dot products.
//   - Z bits 9..7 from i, bits 1..0 from j, bits 6..2 from lane index
//     (handled by a 5-stage Walsh-Hadamard butterfly over one scalar).

__global__ void __launch_bounds__(256)
pauli_expect_kernel(const float* __restrict__ x, float* __restrict__ out,
                    int n_states) {
    const int warp = (blockIdx.x * blockDim.x + threadIdx.x) >> 5;
    const int lane = threadIdx.x & 31;
    if (warp >= n_states) return;

    const float4* xp = reinterpret_cast<const float4*>(x) + (size_t)warp * 256;

    float4 v[8];
#pragma unroll
    for (int i = 0; i < 8; i++) v[i] = xp[i * 32 + lane];

    // ---- per-lane partials ----
    float s[8];
    float z1 = 0.f;  // op8: Z on bit1 (sign from j>>1)
    float z0 = 0.f;  // op9: Z on bit0 (sign from j&1)
#pragma unroll
    for (int i = 0; i < 8; i++) {
        float a0 = v[i].x * v[i].x;
        float a1 = v[i].y * v[i].y;
        float a2 = v[i].z * v[i].z;
        float a3 = v[i].w * v[i].w;
        float p01 = a0 + a1, p23 = a2 + a3;
        s[i] = p01 + p23;
        z1 += p01 - p23;
        z0 += (a0 - a1) + (a2 - a3);
    }

    float e01 = s[0] + s[1], e23 = s[2] + s[3];
    float e45 = s[4] + s[5], e67 = s[6] + s[7];
    float S  = (e01 + e23) + (e45 + e67);          // total sum of squares
    float z9 = (e01 + e23) - (e45 + e67);          // op0: Z bit9 (i bit2)
    float z8 = (e01 + e45) - (e23 + e67);          // op1: Z bit8 (i bit1)
    float z7 = ((s[0] + s[2]) + (s[4] + s[6]))
             - ((s[1] + s[3]) + (s[5] + s[7]));    // op2: Z bit7 (i bit0)

    // ---- X ops: register-resident pair dots (each unordered pair once, x2 later)
#define DOT4(a, b) ((a).x*(b).x + (a).y*(b).y + (a).z*(b).z + (a).w*(b).w)
    float x9 = DOT4(v[0], v[4]) + DOT4(v[1], v[5])
             + DOT4(v[2], v[6]) + DOT4(v[3], v[7]);   // mask 512 (op10)
    float x8 = DOT4(v[0], v[2]) + DOT4(v[1], v[3])
             + DOT4(v[4], v[6]) + DOT4(v[5], v[7]);   // mask 256 (op11)
    float x7 = DOT4(v[0], v[1]) + DOT4(v[2], v[3])
             + DOT4(v[4], v[5]) + DOT4(v[6], v[7]);   // mask 128 (op12)
#undef DOT4

    // ---- warp reductions ----
    const unsigned FULL = 0xFFFFFFFFu;
#pragma unroll
    for (int o = 16; o > 0; o >>= 1) {
        z9 += __shfl_xor_sync(FULL, z9, o);
        z8 += __shfl_xor_sync(FULL, z8, o);
        z7 += __shfl_xor_sync(FULL, z7, o);
        z1 += __shfl_xor_sync(FULL, z1, o);
        z0 += __shfl_xor_sync(FULL, z0, o);
        x9 += __shfl_xor_sync(FULL, x9, o);
        x8 += __shfl_xor_sync(FULL, x8, o);
        x7 += __shfl_xor_sync(FULL, x7, o);
    }

    // Walsh-Hadamard butterfly over S: after 5 stages, lane L holds
    // sum_t (-1)^{popcount(t & L)} S_t. Lane 2^k = Z on d-bit (k+2) = op (7-k).
    float w = S;
#pragma unroll
    for (int k = 0; k < 5; k++) {
        float p = __shfl_xor_sync(FULL, w, 1 << k);
        w = (lane & (1 << k)) ? (p - w) : (p + w);
    }

    float* o = out + (size_t)warp * 16;
    if (lane == 0) {
        o[0]  = z9;
        o[1]  = z8;
        o[2]  = z7;
        o[8]  = z1;
        o[9]  = z0;
        o[10] = 2.0f * x9;
        o[11] = 2.0f * x8;
        o[12] = 2.0f * x7;
        o[13] = 0.0f;
        o[14] = 0.0f;
        o[15] = 0.0f;
    }
    if (lane == 1)  o[7] = w;
    if (lane == 2)  o[6] = w;
    if (lane == 4)  o[5] = w;
    if (lane == 8)  o[4] = w;
    if (lane == 16) o[3] = w;
}

extern "C" void kernel_launch(void* const* d_in, const int* in_sizes, int n_in,
                              void* d_out, int out_size) {
    const float* x = (const float*)d_in[0];
    float* out = (float*)d_out;
    const int n_states = in_sizes[0] / 1024;     // 4096 for (8,512,1024)
    const int warps_per_block = 8;               // 256 threads
    const int blocks = (n_states + warps_per_block - 1) / warps_per_block;
    pauli_expect_kernel<<<blocks, 256>>>(x, out, n_states);
}